// round 13
// baseline (speedup 1.0000x reference)
#include <cuda_runtime.h>
#include <math.h>
#include <stdint.h>

#define BATCH   256
#define LIDX    765

// Scratch (allocation-free __device__ globals)
__device__ float  g_bufA[33554432];
__device__ float  g_bufB[33554432];
__device__ float  g_wpack[1310720];   // packed weights, all 6 layers
__device__ double g_stats[2 * BATCH];
__device__ float  g_mean[BATCH];
__device__ float  g_istd[BATCH];

// ---------------- helpers ----------------

// mish(x) = x*tanh(softplus(x)) = x*(e^2+2e)/(e^2+2e+2), e = exp(x)
__device__ __forceinline__ float mish_f(float x) {
    if (x > 15.f) return x;
    float e = __expf(x);
    float t = e * (e + 2.f);
    return __fdividef(x * t, t + 2.f);
}

__device__ __forceinline__ void ffma2(unsigned long long& d,
                                      unsigned long long a,
                                      unsigned long long b) {
    asm("fma.rn.f32x2 %0, %1, %2, %0;" : "+l"(d) : "l"(a), "l"(b));
}
__device__ __forceinline__ unsigned long long pack2(float x, float y) {
    unsigned long long r;
    asm("mov.b64 %0, {%1, %2};" : "=l"(r) : "f"(x), "f"(y));
    return r;
}

// ---------------- kernel 0: pack W[o,c,k] -> wp[(k*COUT+o)*CIN + c] ----------------
__global__ void pack_w(const float* __restrict__ W, float* __restrict__ wp,
                       int COUT, int CIN)
{
    int i = blockIdx.x * 256 + threadIdx.x;
    int tot = COUT * CIN * 3;
    if (i >= tot) return;
    int o = i / (CIN * 3);
    int rem = i - o * CIN * 3;
    int c = rem / 3;
    int k = rem - 3 * c;
    wp[(size_t)(k * COUT + o) * CIN + c] = W[i];
}

// ---------------- kernel 1: linear + BN + mish ----------------
__global__ __launch_bounds__(256)
void linear_kernel(const float* __restrict__ trees, const float* __restrict__ Wl,
                   const float* __restrict__ bl, const float* __restrict__ gamma,
                   const float* __restrict__ beta, const float* __restrict__ bmean,
                   const float* __restrict__ bvar, float* __restrict__ act0)
{
    const int m0 = blockIdx.x * 64;
    const int b0 = blockIdx.y * 64;
    __shared__ float As[16][65];
    __shared__ float Bs[16][65];
    const int tid = threadIdx.x, tx = tid & 15, ty = tid >> 4;
    float acc[4][4] = {};
    for (int k0 = 0; k0 < 512; k0 += 16) {
        #pragma unroll
        for (int i = tid; i < 64 * 16; i += 256) {
            int m = i >> 4, kk = i & 15;
            As[kk][m] = Wl[(size_t)(m0 + m) * 512 + k0 + kk];
        }
        #pragma unroll
        for (int i = tid; i < 64 * 16; i += 256) {
            int bb = i >> 4, kk = i & 15;
            Bs[kk][bb] = trees[(size_t)(b0 + bb) * 512 + k0 + kk];
        }
        __syncthreads();
        #pragma unroll
        for (int kk = 0; kk < 16; kk++) {
            float ra[4], rb[4];
            #pragma unroll
            for (int u = 0; u < 4; u++) ra[u] = As[kk][ty * 4 + u];
            #pragma unroll
            for (int v = 0; v < 4; v++) rb[v] = Bs[kk][tx * 4 + v];
            #pragma unroll
            for (int u = 0; u < 4; u++)
                #pragma unroll
                for (int v = 0; v < 4; v++)
                    acc[u][v] = fmaf(ra[u], rb[v], acc[u][v]);
        }
        __syncthreads();
    }
    #pragma unroll
    for (int u = 0; u < 4; u++) {
        int m = m0 + ty * 4 + u;
        float sc = rsqrtf(bvar[m] + 1e-5f) * gamma[m];
        float bm = bmean[m], bt = beta[m], bi = bl[m];
        #pragma unroll
        for (int v = 0; v < 4; v++) {
            int bb = b0 + tx * 4 + v;
            float y = acc[u][v] + bi;
            y = (y - bm) * sc + bt;
            act0[(size_t)bb * 4096 + m] = mish_f(y);
        }
    }
}

// ---------------- dense-factorized conv ----------------
// Y[(k,o), s] = sum_c Wp[k*COUT+o, c] * xf(X[b, c, s])   (dense GEMM, 96 rows/CTA)
// out[b, o, n] = (n==0)?0 : Y[0,o,i0(n)] + Y[1,o,i1(n)] + Y[2,o,i2(n)] + bias[o]
// XFORM: 0 = identity, 1 = (x-mean)*istd, 2 = mish((x-mean)*istd)
template<int CIN, int COUT, int XFORM>
__global__ __launch_bounds__(256, 1)
void conv_dense(const float* __restrict__ act, const int* __restrict__ idx,
                const float* __restrict__ wp, const float* __restrict__ bias,
                const float* __restrict__ mean, const float* __restrict__ istd,
                float* __restrict__ raw, double* __restrict__ stats)
{
    constexpr int KC   = (CIN < 32) ? CIN : 32;     // K-chunk
    constexpr int NC   = CIN / KC;
    constexpr int XR   = KC / 4;                    // float4/thread, X chunk
    constexpr int AV   = KC / 4;                    // float4 per A row
    constexpr int ATOT = 96 * AV;
    constexpr int AR   = (ATOT + 255) / 256;

    extern __shared__ float smem[];
    float*  Xs   = smem;                      // [2][KC][256]
    float*  As   = smem + 2 * KC * 256;       // [2][KC][96]
    float*  Ys   = smem;                      // [96][258] (aliases Xs/As after mainloop)
    int*    sidx = (int*)(smem + 24768);      // [768]
    double* red  = (double*)(smem + 24768 + 768);  // [512]

    const int b   = blockIdx.y;
    const int m0  = blockIdx.x * 32;
    const int tid = threadIdx.x;
    const int tx  = tid & 15, ty = tid >> 4;

    const float4* xsrc = (const float4*)(act + (size_t)b * CIN * 256);
    const float4* wp4  = (const float4*)wp;

    float mb = 0.f, isb = 1.f;
    if (XFORM) { mb = mean[b]; isb = istd[b]; }

    for (int i = tid; i < LIDX; i += 256) sidx[i] = idx[b * LIDX + i];

    unsigned long long acc[6][8];
    #pragma unroll
    for (int u = 0; u < 6; u++)
        #pragma unroll
        for (int q = 0; q < 8; q++) acc[u][q] = 0ULL;

    float4 xreg[XR];
    float4 areg[AR];

    auto ldg_chunk = [&](int c) {
        #pragma unroll
        for (int r = 0; r < XR; r++)
            xreg[r] = xsrc[c * (KC * 64) + tid + 256 * r];
        #pragma unroll
        for (int t = 0; t < AR; t++) {
            int i = tid + 256 * t;
            if (AR * 256 == ATOT || i < ATOT) {
                int r = i / AV, cc = i - r * AV;
                int k = r >> 5, o = r & 31;
                areg[t] = wp4[(size_t)(k * COUT + m0 + o) * (CIN / 4) + c * AV + cc];
            }
        }
    };

    auto sts_chunk = [&](int buf) {
        float* Xb = Xs + buf * KC * 256;
        #pragma unroll
        for (int r = 0; r < XR; r++) {
            float4 v = xreg[r];
            if (XFORM) {
                v.x = (v.x - mb) * isb; v.y = (v.y - mb) * isb;
                v.z = (v.z - mb) * isb; v.w = (v.w - mb) * isb;
                if (XFORM == 2) {
                    v.x = mish_f(v.x); v.y = mish_f(v.y);
                    v.z = mish_f(v.z); v.w = mish_f(v.w);
                }
            }
            ((float4*)Xb)[tid + 256 * r] = v;
        }
        float* Ab = As + buf * KC * 96;
        #pragma unroll
        for (int t = 0; t < AR; t++) {
            int i = tid + 256 * t;
            if (AR * 256 == ATOT || i < ATOT) {
                int r = i / AV, cc = i - r * AV;
                Ab[(cc * 4 + 0) * 96 + r] = areg[t].x;
                Ab[(cc * 4 + 1) * 96 + r] = areg[t].y;
                Ab[(cc * 4 + 2) * 96 + r] = areg[t].z;
                Ab[(cc * 4 + 3) * 96 + r] = areg[t].w;
            }
        }
    };

    auto fma_chunk = [&](int buf) {
        const unsigned long long* Bb =
            (const unsigned long long*)(Xs + buf * KC * 256);
        const float* Ab = As + buf * KC * 96 + ty * 6;
        #pragma unroll 8
        for (int kk = 0; kk < KC; kk++) {
            unsigned long long bf[8];
            #pragma unroll
            for (int q = 0; q < 8; q++) bf[q] = Bb[kk * 128 + tx + 16 * q];
            #pragma unroll
            for (int u = 0; u < 6; u++) {
                float a = Ab[kk * 96 + u];
                unsigned long long a2 = pack2(a, a);
                #pragma unroll
                for (int q = 0; q < 8; q++) ffma2(acc[u][q], a2, bf[q]);
            }
        }
    };

    // ---- software-pipelined main loop (LDG overlapped with FMA) ----
    ldg_chunk(0);
    sts_chunk(0);
    __syncthreads();
    for (int c = 0; c < NC; c++) {
        if (c + 1 < NC) ldg_chunk(c + 1);
        fma_chunk(c & 1);
        __syncthreads();
        if (c + 1 < NC) { sts_chunk((c + 1) & 1); __syncthreads(); }
    }

    // ---- epilogue: Y tile -> smem, gather, bias, stats ----
    #pragma unroll
    for (int u = 0; u < 6; u++) {
        unsigned long long* yrow =
            (unsigned long long*)(Ys + (ty * 6 + u) * 258);
        #pragma unroll
        for (int q = 0; q < 8; q++) yrow[tx + 16 * q] = acc[u][q];
    }
    __syncthreads();

    int j0 = 0, j1 = 0, j2 = 0;
    if (tid) {
        j0 = sidx[3 * tid - 3];
        j1 = sidx[3 * tid - 2];
        j2 = sidx[3 * tid - 1];
    }
    float bsum = 0.f, bssq = 0.f;
    float* outb = raw + ((size_t)b * COUT + m0) * 256;
    #pragma unroll 4
    for (int o = 0; o < 32; o++) {
        float v = 0.f;
        if (tid) {
            v = Ys[o * 258 + j0] + Ys[(32 + o) * 258 + j1] +
                Ys[(64 + o) * 258 + j2] + bias[m0 + o];
        }
        outb[o * 256 + tid] = v;
        bsum += v;
        bssq += v * v;
    }

    red[tid] = (double)bsum;
    red[256 + tid] = (double)bssq;
    __syncthreads();
    #pragma unroll
    for (int off = 128; off > 0; off >>= 1) {
        if (tid < off) {
            red[tid] += red[tid + off];
            red[256 + tid] += red[256 + tid + off];
        }
        __syncthreads();
    }
    if (tid == 0) {
        atomicAdd(&stats[b], red[0]);
        atomicAdd(&stats[BATCH + b], red[256]);
    }
}

// ---------------- finalize per-batch LN statistics ----------------
__global__ void finalize_kernel(const double* __restrict__ stats,
                                float* __restrict__ mean, float* __restrict__ istd,
                                double cnt)
{
    int b = threadIdx.x;
    double s = stats[b], ss = stats[BATCH + b];
    double m = s / cnt;
    double var = (ss - cnt * m * m) / (cnt - 1.0);
    if (var < 0.0) var = 0.0;
    mean[b] = (float)m;
    istd[b] = 1.f / ((float)sqrt(var) + 1e-5f);
}

// ---------------- final normalize + mish -> out ----------------
__global__ __launch_bounds__(256)
void norm_final(const float* __restrict__ raw, const float* __restrict__ mean,
                const float* __restrict__ istd, float* __restrict__ out)
{
    const int PER4 = 512 * 256 / 4;
    const int total4 = BATCH * PER4;
    const float4* src = reinterpret_cast<const float4*>(raw);
    float4* dst = reinterpret_cast<float4*>(out);
    for (int i = blockIdx.x * blockDim.x + threadIdx.x; i < total4;
         i += gridDim.x * blockDim.x) {
        int b = i / PER4;
        float mb = mean[b], isb = istd[b];
        float4 v = src[i];
        v.x = mish_f((v.x - mb) * isb);
        v.y = mish_f((v.y - mb) * isb);
        v.z = mish_f((v.z - mb) * isb);
        v.w = mish_f((v.w - mb) * isb);
        dst[i] = v;
    }
}

// ---------------- launch ----------------

static constexpr int CONV_SMEM = (24768 + 768) * 4 + 512 * 8;  // 106240 B

extern "C" void kernel_launch(void* const* d_in, const int* in_sizes, int n_in,
                              void* d_out, int out_size)
{
    (void)in_sizes; (void)n_in; (void)out_size;
    const float* trees   = (const float*)d_in[0];
    const int*   indexes = (const int*)d_in[1];
    const float* W_lin   = (const float*)d_in[2];
    const float* b_lin   = (const float*)d_in[3];
    const float* bn_g    = (const float*)d_in[4];
    const float* bn_b    = (const float*)d_in[5];
    const float* bn_m    = (const float*)d_in[6];
    const float* bn_v    = (const float*)d_in[7];
    float* out = (float*)d_out;

    float *bufA, *bufB, *gmean, *gistd, *wpack;
    double* stats;
    cudaGetSymbolAddress((void**)&bufA,  g_bufA);
    cudaGetSymbolAddress((void**)&bufB,  g_bufB);
    cudaGetSymbolAddress((void**)&gmean, g_mean);
    cudaGetSymbolAddress((void**)&gistd, g_istd);
    cudaGetSymbolAddress((void**)&wpack, g_wpack);
    cudaGetSymbolAddress((void**)&stats, g_stats);

    cudaFuncSetAttribute(conv_dense<16, 32, 0>,
        cudaFuncAttributeMaxDynamicSharedMemorySize, CONV_SMEM);
    cudaFuncSetAttribute(conv_dense<32, 64, 1>,
        cudaFuncAttributeMaxDynamicSharedMemorySize, CONV_SMEM);
    cudaFuncSetAttribute(conv_dense<64, 128, 2>,
        cudaFuncAttributeMaxDynamicSharedMemorySize, CONV_SMEM);
    cudaFuncSetAttribute(conv_dense<128, 256, 2>,
        cudaFuncAttributeMaxDynamicSharedMemorySize, CONV_SMEM);
    cudaFuncSetAttribute(conv_dense<256, 512, 2>,
        cudaFuncAttributeMaxDynamicSharedMemorySize, CONV_SMEM);
    cudaFuncSetAttribute(conv_dense<512, 512, 2>,
        cudaFuncAttributeMaxDynamicSharedMemorySize, CONV_SMEM);

    // Pack all 6 weight tensors: wp[(k*COUT+o)*CIN + c] = W[o,c,k]
    static const int CH[7]    = {16, 32, 64, 128, 256, 512, 512};
    static const int WPOFF[6] = {0, 1536, 7680, 32256, 130560, 523776};
    for (int i = 0; i < 6; i++) {
        int cin = CH[i], cout = CH[i + 1];
        int tot = cout * cin * 3;
        pack_w<<<(tot + 255) / 256, 256>>>((const float*)d_in[8 + 2 * i],
                                           wpack + WPOFF[i], cout, cin);
    }

    // linear + BN + mish -> bufA (viewed as (B, 16, 256))
    linear_kernel<<<dim3(64, 4), 256>>>(
        trees, W_lin, b_lin, bn_g, bn_b, bn_m, bn_v, bufA);

#define CONVL(I, CIN, COUT, XF, SRC, DST)                                         \
    cudaMemsetAsync(stats, 0, sizeof(double) * 2 * BATCH);                        \
    conv_dense<CIN, COUT, XF>                                                     \
        <<<dim3(COUT / 32, BATCH), 256, CONV_SMEM>>>(                             \
            SRC, indexes, wpack + WPOFF[I],                                       \
            (const float*)d_in[9 + 2 * I], gmean, gistd, DST, stats);             \
    finalize_kernel<<<1, BATCH>>>(stats, gmean, gistd, (double)(COUT * 256));

    CONVL(0,  16,  32, 0, bufA, bufB)
    CONVL(1,  32,  64, 1, bufB, bufA)
    CONVL(2,  64, 128, 2, bufA, bufB)
    CONVL(3, 128, 256, 2, bufB, bufA)
    CONVL(4, 256, 512, 2, bufA, bufB)
    CONVL(5, 512, 512, 2, bufB, bufA)
#undef CONVL

    // final: out = mish(LN(raw5))
    norm_final<<<2048, 256>>>(bufA, gmean, gistd, out);
}

// round 14
// speedup vs baseline: 1.0046x; 1.0046x over previous
#include <cuda_runtime.h>
#include <math.h>
#include <stdint.h>

#define BATCH   256
#define LIDX    765

// Scratch (allocation-free __device__ globals)
__device__ float  g_bufA[33554432];
__device__ float  g_bufB[33554432];
__device__ float  g_wpack[1310720];   // packed weights, all 6 layers
__device__ double g_stats[2 * BATCH];
__device__ float  g_mean[BATCH];
__device__ float  g_istd[BATCH];

// ---------------- helpers ----------------

// mish(x) = x*tanh(softplus(x)) = x*(e^2+2e)/(e^2+2e+2), e = exp(x)
__device__ __forceinline__ float mish_f(float x) {
    if (x > 15.f) return x;
    float e = __expf(x);
    float t = e * (e + 2.f);
    return __fdividef(x * t, t + 2.f);
}

__device__ __forceinline__ void ffma2(unsigned long long& d,
                                      unsigned long long a,
                                      unsigned long long b) {
    asm("fma.rn.f32x2 %0, %1, %2, %0;" : "+l"(d) : "l"(a), "l"(b));
}
__device__ __forceinline__ unsigned long long pack2(float x, float y) {
    unsigned long long r;
    asm("mov.b64 %0, {%1, %2};" : "=l"(r) : "f"(x), "f"(y));
    return r;
}

// ---------------- kernel 0: pack W[o,c,k] -> wp[(k*COUT+o)*CIN + c] ----------------
__global__ void pack_w(const float* __restrict__ W, float* __restrict__ wp,
                       int COUT, int CIN)
{
    int i = blockIdx.x * 256 + threadIdx.x;
    int tot = COUT * CIN * 3;
    if (i >= tot) return;
    int o = i / (CIN * 3);
    int rem = i - o * CIN * 3;
    int c = rem / 3;
    int k = rem - 3 * c;
    wp[(size_t)(k * COUT + o) * CIN + c] = W[i];
}

// ---------------- kernel 1: linear + BN + mish ----------------
__global__ __launch_bounds__(256)
void linear_kernel(const float* __restrict__ trees, const float* __restrict__ Wl,
                   const float* __restrict__ bl, const float* __restrict__ gamma,
                   const float* __restrict__ beta, const float* __restrict__ bmean,
                   const float* __restrict__ bvar, float* __restrict__ act0)
{
    const int m0 = blockIdx.x * 64;
    const int b0 = blockIdx.y * 64;
    __shared__ float As[16][65];
    __shared__ float Bs[16][65];
    const int tid = threadIdx.x, tx = tid & 15, ty = tid >> 4;
    float acc[4][4] = {};
    for (int k0 = 0; k0 < 512; k0 += 16) {
        #pragma unroll
        for (int i = tid; i < 64 * 16; i += 256) {
            int m = i >> 4, kk = i & 15;
            As[kk][m] = Wl[(size_t)(m0 + m) * 512 + k0 + kk];
        }
        #pragma unroll
        for (int i = tid; i < 64 * 16; i += 256) {
            int bb = i >> 4, kk = i & 15;
            Bs[kk][bb] = trees[(size_t)(b0 + bb) * 512 + k0 + kk];
        }
        __syncthreads();
        #pragma unroll
        for (int kk = 0; kk < 16; kk++) {
            float ra[4], rb[4];
            #pragma unroll
            for (int u = 0; u < 4; u++) ra[u] = As[kk][ty * 4 + u];
            #pragma unroll
            for (int v = 0; v < 4; v++) rb[v] = Bs[kk][tx * 4 + v];
            #pragma unroll
            for (int u = 0; u < 4; u++)
                #pragma unroll
                for (int v = 0; v < 4; v++)
                    acc[u][v] = fmaf(ra[u], rb[v], acc[u][v]);
        }
        __syncthreads();
    }
    #pragma unroll
    for (int u = 0; u < 4; u++) {
        int m = m0 + ty * 4 + u;
        float sc = rsqrtf(bvar[m] + 1e-5f) * gamma[m];
        float bm = bmean[m], bt = beta[m], bi = bl[m];
        #pragma unroll
        for (int v = 0; v < 4; v++) {
            int bb = b0 + tx * 4 + v;
            float y = acc[u][v] + bi;
            y = (y - bm) * sc + bt;
            act0[(size_t)bb * 4096 + m] = mish_f(y);
        }
    }
}

// ---------------- dense-factorized conv ----------------
// Y[(k,o), s] = sum_c Wp[k*COUT+o, c] * xf(X[b, c, s])   (dense GEMM, 96 rows/CTA)
// out[b, o, n] = (n==0)?0 : Y[0,o,i0(n)] + Y[1,o,i1(n)] + Y[2,o,i2(n)] + bias[o]
// XFORM: 0 = identity, 1 = (x-mean)*istd, 2 = mish((x-mean)*istd)
template<int CIN, int COUT, int XFORM>
__global__ __launch_bounds__(256, 1)
void conv_dense(const float* __restrict__ act, const int* __restrict__ idx,
                const float* __restrict__ wp, const float* __restrict__ bias,
                const float* __restrict__ mean, const float* __restrict__ istd,
                float* __restrict__ raw, double* __restrict__ stats)
{
    constexpr int KC   = (CIN < 32) ? CIN : 32;     // K-chunk
    constexpr int NC   = CIN / KC;
    constexpr int XR   = KC / 4;                    // float4/thread, X chunk
    constexpr int AV   = KC / 4;                    // float4 per A row
    constexpr int ATOT = 96 * AV;
    constexpr int AR   = (ATOT + 255) / 256;

    extern __shared__ float smem[];
    float*  Xs   = smem;                      // [2][KC][256]
    float*  As   = smem + 2 * KC * 256;       // [2][KC][96]
    float*  Ys   = smem;                      // [96][258] (aliases Xs/As after mainloop)
    int*    sidx = (int*)(smem + 24768);      // [768]
    double* red  = (double*)(smem + 24768 + 768);  // [512]

    const int b   = blockIdx.y;
    const int m0  = blockIdx.x * 32;
    const int tid = threadIdx.x;
    const int tx  = tid & 15, ty = tid >> 4;

    const float4* xsrc = (const float4*)(act + (size_t)b * CIN * 256);
    const float4* wp4  = (const float4*)wp;

    float mb = 0.f, isb = 1.f;
    if (XFORM) { mb = mean[b]; isb = istd[b]; }

    for (int i = tid; i < LIDX; i += 256) sidx[i] = idx[b * LIDX + i];

    unsigned long long acc[6][8];
    #pragma unroll
    for (int u = 0; u < 6; u++)
        #pragma unroll
        for (int q = 0; q < 8; q++) acc[u][q] = 0ULL;

    float4 xreg[XR];
    float4 areg[AR];

    auto ldg_chunk = [&](int c) {
        #pragma unroll
        for (int r = 0; r < XR; r++)
            xreg[r] = xsrc[c * (KC * 64) + tid + 256 * r];
        #pragma unroll
        for (int t = 0; t < AR; t++) {
            int i = tid + 256 * t;
            if (AR * 256 == ATOT || i < ATOT) {
                int r = i / AV, cc = i - r * AV;
                int k = r >> 5, o = r & 31;
                areg[t] = wp4[(size_t)(k * COUT + m0 + o) * (CIN / 4) + c * AV + cc];
            }
        }
    };

    auto sts_chunk = [&](int buf) {
        float* Xb = Xs + buf * KC * 256;
        #pragma unroll
        for (int r = 0; r < XR; r++) {
            float4 v = xreg[r];
            if (XFORM) {
                v.x = (v.x - mb) * isb; v.y = (v.y - mb) * isb;
                v.z = (v.z - mb) * isb; v.w = (v.w - mb) * isb;
                if (XFORM == 2) {
                    v.x = mish_f(v.x); v.y = mish_f(v.y);
                    v.z = mish_f(v.z); v.w = mish_f(v.w);
                }
            }
            ((float4*)Xb)[tid + 256 * r] = v;
        }
        float* Ab = As + buf * KC * 96;
        #pragma unroll
        for (int t = 0; t < AR; t++) {
            int i = tid + 256 * t;
            if (AR * 256 == ATOT || i < ATOT) {
                int r = i / AV, cc = i - r * AV;
                Ab[(cc * 4 + 0) * 96 + r] = areg[t].x;
                Ab[(cc * 4 + 1) * 96 + r] = areg[t].y;
                Ab[(cc * 4 + 2) * 96 + r] = areg[t].z;
                Ab[(cc * 4 + 3) * 96 + r] = areg[t].w;
            }
        }
    };

    auto fma_chunk = [&](int buf) {
        const unsigned long long* Bb =
            (const unsigned long long*)(Xs + buf * KC * 256);
        const float* Ab = As + buf * KC * 96 + ty * 6;
        #pragma unroll 8
        for (int kk = 0; kk < KC; kk++) {
            unsigned long long bf[8];
            #pragma unroll
            for (int q = 0; q < 8; q++) bf[q] = Bb[kk * 128 + tx + 16 * q];
            #pragma unroll
            for (int u = 0; u < 6; u++) {
                float a = Ab[kk * 96 + u];
                unsigned long long a2 = pack2(a, a);
                #pragma unroll
                for (int q = 0; q < 8; q++) ffma2(acc[u][q], a2, bf[q]);
            }
        }
    };

    // ---- software-pipelined main loop (LDG overlapped with FMA) ----
    ldg_chunk(0);
    sts_chunk(0);
    __syncthreads();
    for (int c = 0; c < NC; c++) {
        if (c + 1 < NC) ldg_chunk(c + 1);
        fma_chunk(c & 1);
        __syncthreads();
        if (c + 1 < NC) { sts_chunk((c + 1) & 1); __syncthreads(); }
    }

    // ---- epilogue: Y tile -> smem, gather, bias, stats ----
    #pragma unroll
    for (int u = 0; u < 6; u++) {
        unsigned long long* yrow =
            (unsigned long long*)(Ys + (ty * 6 + u) * 258);
        #pragma unroll
        for (int q = 0; q < 8; q++) yrow[tx + 16 * q] = acc[u][q];
    }
    __syncthreads();

    int j0 = 0, j1 = 0, j2 = 0;
    if (tid) {
        j0 = sidx[3 * tid - 3];
        j1 = sidx[3 * tid - 2];
        j2 = sidx[3 * tid - 1];
    }
    float bsum = 0.f, bssq = 0.f;
    float* outb = raw + ((size_t)b * COUT + m0) * 256;
    #pragma unroll 4
    for (int o = 0; o < 32; o++) {
        float v = 0.f;
        if (tid) {
            v = Ys[o * 258 + j0] + Ys[(32 + o) * 258 + j1] +
                Ys[(64 + o) * 258 + j2] + bias[m0 + o];
        }
        outb[o * 256 + tid] = v;
        bsum += v;
        bssq += v * v;
    }

    red[tid] = (double)bsum;
    red[256 + tid] = (double)bssq;
    __syncthreads();
    #pragma unroll
    for (int off = 128; off > 0; off >>= 1) {
        if (tid < off) {
            red[tid] += red[tid + off];
            red[256 + tid] += red[256 + tid + off];
        }
        __syncthreads();
    }
    if (tid == 0) {
        atomicAdd(&stats[b], red[0]);
        atomicAdd(&stats[BATCH + b], red[256]);
    }
}

// ---------------- finalize per-batch LN statistics ----------------
__global__ void finalize_kernel(const double* __restrict__ stats,
                                float* __restrict__ mean, float* __restrict__ istd,
                                double cnt)
{
    int b = threadIdx.x;
    double s = stats[b], ss = stats[BATCH + b];
    double m = s / cnt;
    double var = (ss - cnt * m * m) / (cnt - 1.0);
    if (var < 0.0) var = 0.0;
    mean[b] = (float)m;
    istd[b] = 1.f / ((float)sqrt(var) + 1e-5f);
}

// ---------------- final normalize + mish -> out ----------------
__global__ __launch_bounds__(256)
void norm_final(const float* __restrict__ raw, const float* __restrict__ mean,
                const float* __restrict__ istd, float* __restrict__ out)
{
    const int PER4 = 512 * 256 / 4;
    const int total4 = BATCH * PER4;
    const float4* src = reinterpret_cast<const float4*>(raw);
    float4* dst = reinterpret_cast<float4*>(out);
    for (int i = blockIdx.x * blockDim.x + threadIdx.x; i < total4;
         i += gridDim.x * blockDim.x) {
        int b = i / PER4;
        float mb = mean[b], isb = istd[b];
        float4 v = src[i];
        v.x = mish_f((v.x - mb) * isb);
        v.y = mish_f((v.y - mb) * isb);
        v.z = mish_f((v.z - mb) * isb);
        v.w = mish_f((v.w - mb) * isb);
        dst[i] = v;
    }
}

// ---------------- launch ----------------

static constexpr int CONV_SMEM = (24768 + 768) * 4 + 512 * 8;  // 106240 B

extern "C" void kernel_launch(void* const* d_in, const int* in_sizes, int n_in,
                              void* d_out, int out_size)
{
    (void)in_sizes; (void)n_in; (void)out_size;
    const float* trees   = (const float*)d_in[0];
    const int*   indexes = (const int*)d_in[1];
    const float* W_lin   = (const float*)d_in[2];
    const float* b_lin   = (const float*)d_in[3];
    const float* bn_g    = (const float*)d_in[4];
    const float* bn_b    = (const float*)d_in[5];
    const float* bn_m    = (const float*)d_in[6];
    const float* bn_v    = (const float*)d_in[7];
    float* out = (float*)d_out;

    float *bufA, *bufB, *gmean, *gistd, *wpack;
    double* stats;
    cudaGetSymbolAddress((void**)&bufA,  g_bufA);
    cudaGetSymbolAddress((void**)&bufB,  g_bufB);
    cudaGetSymbolAddress((void**)&gmean, g_mean);
    cudaGetSymbolAddress((void**)&gistd, g_istd);
    cudaGetSymbolAddress((void**)&wpack, g_wpack);
    cudaGetSymbolAddress((void**)&stats, g_stats);

    cudaFuncSetAttribute(conv_dense<16, 32, 0>,
        cudaFuncAttributeMaxDynamicSharedMemorySize, CONV_SMEM);
    cudaFuncSetAttribute(conv_dense<32, 64, 1>,
        cudaFuncAttributeMaxDynamicSharedMemorySize, CONV_SMEM);
    cudaFuncSetAttribute(conv_dense<64, 128, 2>,
        cudaFuncAttributeMaxDynamicSharedMemorySize, CONV_SMEM);
    cudaFuncSetAttribute(conv_dense<128, 256, 2>,
        cudaFuncAttributeMaxDynamicSharedMemorySize, CONV_SMEM);
    cudaFuncSetAttribute(conv_dense<256, 512, 2>,
        cudaFuncAttributeMaxDynamicSharedMemorySize, CONV_SMEM);
    cudaFuncSetAttribute(conv_dense<512, 512, 2>,
        cudaFuncAttributeMaxDynamicSharedMemorySize, CONV_SMEM);

    // Pack all 6 weight tensors: wp[(k*COUT+o)*CIN + c] = W[o,c,k]
    static const int CH[7]    = {16, 32, 64, 128, 256, 512, 512};
    static const int WPOFF[6] = {0, 1536, 7680, 32256, 130560, 523776};
    for (int i = 0; i < 6; i++) {
        int cin = CH[i], cout = CH[i + 1];
        int tot = cout * cin * 3;
        pack_w<<<(tot + 255) / 256, 256>>>((const float*)d_in[8 + 2 * i],
                                           wpack + WPOFF[i], cout, cin);
    }

    // linear + BN + mish -> bufA (viewed as (B, 16, 256))
    linear_kernel<<<dim3(64, 4), 256>>>(
        trees, W_lin, b_lin, bn_g, bn_b, bn_m, bn_v, bufA);

#define CONVL(I, CIN, COUT, XF, SRC, DST)                                         \
    cudaMemsetAsync(stats, 0, sizeof(double) * 2 * BATCH);                        \
    conv_dense<CIN, COUT, XF>                                                     \
        <<<dim3(COUT / 32, BATCH), 256, CONV_SMEM>>>(                             \
            SRC, indexes, wpack + WPOFF[I],                                       \
            (const float*)d_in[9 + 2 * I], gmean, gistd, DST, stats);             \
    finalize_kernel<<<1, BATCH>>>(stats, gmean, gistd, (double)(COUT * 256));

    CONVL(0,  16,  32, 0, bufA, bufB)
    CONVL(1,  32,  64, 1, bufB, bufA)
    CONVL(2,  64, 128, 2, bufA, bufB)
    CONVL(3, 128, 256, 2, bufB, bufA)
    CONVL(4, 256, 512, 2, bufA, bufB)
    CONVL(5, 512, 512, 2, bufB, bufA)
#undef CONVL

    // final: out = mish(LN(raw5))
    norm_final<<<2048, 256>>>(bufA, gmean, gistd, out);
}

// round 15
// speedup vs baseline: 1.0048x; 1.0003x over previous
#include <cuda_runtime.h>
#include <math.h>
#include <stdint.h>

#define BATCH   256
#define LIDX    765

// Scratch (allocation-free __device__ globals)
__device__ float  g_bufA[33554432];
__device__ float  g_bufB[33554432];
__device__ float  g_wpack[1310720];   // packed weights, all 6 layers
__device__ double g_stats[2 * BATCH];
__device__ float  g_mean[BATCH];
__device__ float  g_istd[BATCH];

// ---------------- helpers ----------------

// mish(x) = x*tanh(softplus(x)) = x*(e^2+2e)/(e^2+2e+2), e = exp(x)
__device__ __forceinline__ float mish_f(float x) {
    if (x > 15.f) return x;
    float e = __expf(x);
    float t = e * (e + 2.f);
    return __fdividef(x * t, t + 2.f);
}

__device__ __forceinline__ void ffma2(unsigned long long& d,
                                      unsigned long long a,
                                      unsigned long long b) {
    asm("fma.rn.f32x2 %0, %1, %2, %0;" : "+l"(d) : "l"(a), "l"(b));
}
__device__ __forceinline__ unsigned long long pack2(float x, float y) {
    unsigned long long r;
    asm("mov.b64 %0, {%1, %2};" : "=l"(r) : "f"(x), "f"(y));
    return r;
}

// ---------------- kernel 0: pack W[o,c,k] -> wp[(k*COUT+o)*CIN + c] ----------------
__global__ void pack_w(const float* __restrict__ W, float* __restrict__ wp,
                       int COUT, int CIN)
{
    int i = blockIdx.x * 256 + threadIdx.x;
    int tot = COUT * CIN * 3;
    if (i >= tot) return;
    int o = i / (CIN * 3);
    int rem = i - o * CIN * 3;
    int c = rem / 3;
    int k = rem - 3 * c;
    wp[(size_t)(k * COUT + o) * CIN + c] = W[i];
}

// ---------------- kernel 1: linear + BN + mish ----------------
__global__ __launch_bounds__(256)
void linear_kernel(const float* __restrict__ trees, const float* __restrict__ Wl,
                   const float* __restrict__ bl, const float* __restrict__ gamma,
                   const float* __restrict__ beta, const float* __restrict__ bmean,
                   const float* __restrict__ bvar, float* __restrict__ act0)
{
    const int m0 = blockIdx.x * 64;
    const int b0 = blockIdx.y * 64;
    __shared__ float As[16][65];
    __shared__ float Bs[16][65];
    const int tid = threadIdx.x, tx = tid & 15, ty = tid >> 4;
    float acc[4][4] = {};
    for (int k0 = 0; k0 < 512; k0 += 16) {
        #pragma unroll
        for (int i = tid; i < 64 * 16; i += 256) {
            int m = i >> 4, kk = i & 15;
            As[kk][m] = Wl[(size_t)(m0 + m) * 512 + k0 + kk];
        }
        #pragma unroll
        for (int i = tid; i < 64 * 16; i += 256) {
            int bb = i >> 4, kk = i & 15;
            Bs[kk][bb] = trees[(size_t)(b0 + bb) * 512 + k0 + kk];
        }
        __syncthreads();
        #pragma unroll
        for (int kk = 0; kk < 16; kk++) {
            float ra[4], rb[4];
            #pragma unroll
            for (int u = 0; u < 4; u++) ra[u] = As[kk][ty * 4 + u];
            #pragma unroll
            for (int v = 0; v < 4; v++) rb[v] = Bs[kk][tx * 4 + v];
            #pragma unroll
            for (int u = 0; u < 4; u++)
                #pragma unroll
                for (int v = 0; v < 4; v++)
                    acc[u][v] = fmaf(ra[u], rb[v], acc[u][v]);
        }
        __syncthreads();
    }
    #pragma unroll
    for (int u = 0; u < 4; u++) {
        int m = m0 + ty * 4 + u;
        float sc = rsqrtf(bvar[m] + 1e-5f) * gamma[m];
        float bm = bmean[m], bt = beta[m], bi = bl[m];
        #pragma unroll
        for (int v = 0; v < 4; v++) {
            int bb = b0 + tx * 4 + v;
            float y = acc[u][v] + bi;
            y = (y - bm) * sc + bt;
            act0[(size_t)bb * 4096 + m] = mish_f(y);
        }
    }
}

// ---------------- dense-factorized conv ----------------
// Y[(k,o), s] = sum_c Wp[k*COUT+o, c] * xf(X[b, c, s])   (dense GEMM, 96 rows/CTA)
// out[b, o, n] = (n==0)?0 : Y[0,o,i0(n)] + Y[1,o,i1(n)] + Y[2,o,i2(n)] + bias[o]
// XFORM: 0 = identity, 1 = (x-mean)*istd, 2 = mish((x-mean)*istd)
template<int CIN, int COUT, int XFORM>
__global__ __launch_bounds__(256, 1)
void conv_dense(const float* __restrict__ act, const int* __restrict__ idx,
                const float* __restrict__ wp, const float* __restrict__ bias,
                const float* __restrict__ mean, const float* __restrict__ istd,
                float* __restrict__ raw, double* __restrict__ stats)
{
    constexpr int KC   = (CIN < 32) ? CIN : 32;     // K-chunk
    constexpr int NC   = CIN / KC;
    constexpr int XR   = KC / 4;                    // float4/thread, X chunk
    constexpr int AV   = KC / 4;                    // float4 per A row
    constexpr int ATOT = 96 * AV;
    constexpr int AR   = (ATOT + 255) / 256;

    extern __shared__ float smem[];
    float*  Xs   = smem;                      // [2][KC][256]
    float*  As   = smem + 2 * KC * 256;       // [2][KC][96]
    float*  Ys   = smem;                      // [96][258] (aliases Xs/As after mainloop)
    int*    sidx = (int*)(smem + 24768);      // [768]
    double* red  = (double*)(smem + 24768 + 768);  // [512]

    const int b   = blockIdx.y;
    const int m0  = blockIdx.x * 32;
    const int tid = threadIdx.x;
    const int tx  = tid & 15, ty = tid >> 4;

    const float4* xsrc = (const float4*)(act + (size_t)b * CIN * 256);
    const float4* wp4  = (const float4*)wp;

    float mb = 0.f, isb = 1.f;
    if (XFORM) { mb = mean[b]; isb = istd[b]; }

    for (int i = tid; i < LIDX; i += 256) sidx[i] = idx[b * LIDX + i];

    unsigned long long acc[6][8];
    #pragma unroll
    for (int u = 0; u < 6; u++)
        #pragma unroll
        for (int q = 0; q < 8; q++) acc[u][q] = 0ULL;

    float4 xreg[XR];
    float4 areg[AR];

    auto ldg_chunk = [&](int c) {
        #pragma unroll
        for (int r = 0; r < XR; r++)
            xreg[r] = xsrc[c * (KC * 64) + tid + 256 * r];
        #pragma unroll
        for (int t = 0; t < AR; t++) {
            int i = tid + 256 * t;
            if (AR * 256 == ATOT || i < ATOT) {
                int r = i / AV, cc = i - r * AV;
                int k = r >> 5, o = r & 31;
                areg[t] = wp4[(size_t)(k * COUT + m0 + o) * (CIN / 4) + c * AV + cc];
            }
        }
    };

    auto sts_chunk = [&](int buf) {
        float* Xb = Xs + buf * KC * 256;
        #pragma unroll
        for (int r = 0; r < XR; r++) {
            float4 v = xreg[r];
            if (XFORM) {
                v.x = (v.x - mb) * isb; v.y = (v.y - mb) * isb;
                v.z = (v.z - mb) * isb; v.w = (v.w - mb) * isb;
                if (XFORM == 2) {
                    v.x = mish_f(v.x); v.y = mish_f(v.y);
                    v.z = mish_f(v.z); v.w = mish_f(v.w);
                }
            }
            ((float4*)Xb)[tid + 256 * r] = v;
        }
        float* Ab = As + buf * KC * 96;
        #pragma unroll
        for (int t = 0; t < AR; t++) {
            int i = tid + 256 * t;
            if (AR * 256 == ATOT || i < ATOT) {
                int r = i / AV, cc = i - r * AV;
                Ab[(cc * 4 + 0) * 96 + r] = areg[t].x;
                Ab[(cc * 4 + 1) * 96 + r] = areg[t].y;
                Ab[(cc * 4 + 2) * 96 + r] = areg[t].z;
                Ab[(cc * 4 + 3) * 96 + r] = areg[t].w;
            }
        }
    };

    auto fma_chunk = [&](int buf) {
        const unsigned long long* Bb =
            (const unsigned long long*)(Xs + buf * KC * 256);
        const float* Ab = As + buf * KC * 96 + ty * 6;
        #pragma unroll 8
        for (int kk = 0; kk < KC; kk++) {
            unsigned long long bf[8];
            #pragma unroll
            for (int q = 0; q < 8; q++) bf[q] = Bb[kk * 128 + tx + 16 * q];
            #pragma unroll
            for (int u = 0; u < 6; u++) {
                float a = Ab[kk * 96 + u];
                unsigned long long a2 = pack2(a, a);
                #pragma unroll
                for (int q = 0; q < 8; q++) ffma2(acc[u][q], a2, bf[q]);
            }
        }
    };

    // ---- software-pipelined main loop (LDG overlapped with FMA) ----
    ldg_chunk(0);
    sts_chunk(0);
    __syncthreads();
    for (int c = 0; c < NC; c++) {
        if (c + 1 < NC) ldg_chunk(c + 1);
        fma_chunk(c & 1);
        __syncthreads();
        if (c + 1 < NC) { sts_chunk((c + 1) & 1); __syncthreads(); }
    }

    // ---- epilogue: Y tile -> smem, gather, bias, stats ----
    #pragma unroll
    for (int u = 0; u < 6; u++) {
        unsigned long long* yrow =
            (unsigned long long*)(Ys + (ty * 6 + u) * 258);
        #pragma unroll
        for (int q = 0; q < 8; q++) yrow[tx + 16 * q] = acc[u][q];
    }
    __syncthreads();

    int j0 = 0, j1 = 0, j2 = 0;
    if (tid) {
        j0 = sidx[3 * tid - 3];
        j1 = sidx[3 * tid - 2];
        j2 = sidx[3 * tid - 1];
    }
    float bsum = 0.f, bssq = 0.f;
    float* outb = raw + ((size_t)b * COUT + m0) * 256;
    #pragma unroll 4
    for (int o = 0; o < 32; o++) {
        float v = 0.f;
        if (tid) {
            v = Ys[o * 258 + j0] + Ys[(32 + o) * 258 + j1] +
                Ys[(64 + o) * 258 + j2] + bias[m0 + o];
        }
        outb[o * 256 + tid] = v;
        bsum += v;
        bssq += v * v;
    }

    red[tid] = (double)bsum;
    red[256 + tid] = (double)bssq;
    __syncthreads();
    #pragma unroll
    for (int off = 128; off > 0; off >>= 1) {
        if (tid < off) {
            red[tid] += red[tid + off];
            red[256 + tid] += red[256 + tid + off];
        }
        __syncthreads();
    }
    if (tid == 0) {
        atomicAdd(&stats[b], red[0]);
        atomicAdd(&stats[BATCH + b], red[256]);
    }
}

// ---------------- finalize per-batch LN statistics ----------------
__global__ void finalize_kernel(const double* __restrict__ stats,
                                float* __restrict__ mean, float* __restrict__ istd,
                                double cnt)
{
    int b = threadIdx.x;
    double s = stats[b], ss = stats[BATCH + b];
    double m = s / cnt;
    double var = (ss - cnt * m * m) / (cnt - 1.0);
    if (var < 0.0) var = 0.0;
    mean[b] = (float)m;
    istd[b] = 1.f / ((float)sqrt(var) + 1e-5f);
}

// ---------------- final normalize + mish -> out ----------------
__global__ __launch_bounds__(256)
void norm_final(const float* __restrict__ raw, const float* __restrict__ mean,
                const float* __restrict__ istd, float* __restrict__ out)
{
    const int PER4 = 512 * 256 / 4;
    const int total4 = BATCH * PER4;
    const float4* src = reinterpret_cast<const float4*>(raw);
    float4* dst = reinterpret_cast<float4*>(out);
    for (int i = blockIdx.x * blockDim.x + threadIdx.x; i < total4;
         i += gridDim.x * blockDim.x) {
        int b = i / PER4;
        float mb = mean[b], isb = istd[b];
        float4 v = src[i];
        v.x = mish_f((v.x - mb) * isb);
        v.y = mish_f((v.y - mb) * isb);
        v.z = mish_f((v.z - mb) * isb);
        v.w = mish_f((v.w - mb) * isb);
        dst[i] = v;
    }
}

// ---------------- launch ----------------

static constexpr int CONV_SMEM = (24768 + 768) * 4 + 512 * 8;  // 106240 B

extern "C" void kernel_launch(void* const* d_in, const int* in_sizes, int n_in,
                              void* d_out, int out_size)
{
    (void)in_sizes; (void)n_in; (void)out_size;
    const float* trees   = (const float*)d_in[0];
    const int*   indexes = (const int*)d_in[1];
    const float* W_lin   = (const float*)d_in[2];
    const float* b_lin   = (const float*)d_in[3];
    const float* bn_g    = (const float*)d_in[4];
    const float* bn_b    = (const float*)d_in[5];
    const float* bn_m    = (const float*)d_in[6];
    const float* bn_v    = (const float*)d_in[7];
    float* out = (float*)d_out;

    float *bufA, *bufB, *gmean, *gistd, *wpack;
    double* stats;
    cudaGetSymbolAddress((void**)&bufA,  g_bufA);
    cudaGetSymbolAddress((void**)&bufB,  g_bufB);
    cudaGetSymbolAddress((void**)&gmean, g_mean);
    cudaGetSymbolAddress((void**)&gistd, g_istd);
    cudaGetSymbolAddress((void**)&wpack, g_wpack);
    cudaGetSymbolAddress((void**)&stats, g_stats);

    cudaFuncSetAttribute(conv_dense<16, 32, 0>,
        cudaFuncAttributeMaxDynamicSharedMemorySize, CONV_SMEM);
    cudaFuncSetAttribute(conv_dense<32, 64, 1>,
        cudaFuncAttributeMaxDynamicSharedMemorySize, CONV_SMEM);
    cudaFuncSetAttribute(conv_dense<64, 128, 2>,
        cudaFuncAttributeMaxDynamicSharedMemorySize, CONV_SMEM);
    cudaFuncSetAttribute(conv_dense<128, 256, 2>,
        cudaFuncAttributeMaxDynamicSharedMemorySize, CONV_SMEM);
    cudaFuncSetAttribute(conv_dense<256, 512, 2>,
        cudaFuncAttributeMaxDynamicSharedMemorySize, CONV_SMEM);
    cudaFuncSetAttribute(conv_dense<512, 512, 2>,
        cudaFuncAttributeMaxDynamicSharedMemorySize, CONV_SMEM);

    // Pack all 6 weight tensors: wp[(k*COUT+o)*CIN + c] = W[o,c,k]
    static const int CH[7]    = {16, 32, 64, 128, 256, 512, 512};
    static const int WPOFF[6] = {0, 1536, 7680, 32256, 130560, 523776};
    for (int i = 0; i < 6; i++) {
        int cin = CH[i], cout = CH[i + 1];
        int tot = cout * cin * 3;
        pack_w<<<(tot + 255) / 256, 256>>>((const float*)d_in[8 + 2 * i],
                                           wpack + WPOFF[i], cout, cin);
    }

    // linear + BN + mish -> bufA (viewed as (B, 16, 256))
    linear_kernel<<<dim3(64, 4), 256>>>(
        trees, W_lin, b_lin, bn_g, bn_b, bn_m, bn_v, bufA);

#define CONVL(I, CIN, COUT, XF, SRC, DST)                                         \
    cudaMemsetAsync(stats, 0, sizeof(double) * 2 * BATCH);                        \
    conv_dense<CIN, COUT, XF>                                                     \
        <<<dim3(COUT / 32, BATCH), 256, CONV_SMEM>>>(                             \
            SRC, indexes, wpack + WPOFF[I],                                       \
            (const float*)d_in[9 + 2 * I], gmean, gistd, DST, stats);             \
    finalize_kernel<<<1, BATCH>>>(stats, gmean, gistd, (double)(COUT * 256));

    CONVL(0,  16,  32, 0, bufA, bufB)
    CONVL(1,  32,  64, 1, bufB, bufA)
    CONVL(2,  64, 128, 2, bufA, bufB)
    CONVL(3, 128, 256, 2, bufB, bufA)
    CONVL(4, 256, 512, 2, bufA, bufB)
    CONVL(5, 512, 512, 2, bufB, bufA)
#undef CONVL

    // final: out = mish(LN(raw5))
    norm_final<<<2048, 256>>>(bufA, gmean, gistd, out);
}

// round 16
// speedup vs baseline: 1.0055x; 1.0007x over previous
#include <cuda_runtime.h>
#include <math.h>
#include <stdint.h>

#define BATCH   256
#define LIDX    765

// Scratch (allocation-free __device__ globals)
__device__ float  g_bufA[33554432];
__device__ float  g_bufB[33554432];
__device__ float  g_wpack[1310720];   // packed weights, all 6 layers
__device__ double g_stats[2 * BATCH];
__device__ float  g_mean[BATCH];
__device__ float  g_istd[BATCH];

// ---------------- helpers ----------------

// mish(x) = x*tanh(softplus(x)) = x*(e^2+2e)/(e^2+2e+2), e = exp(x)
__device__ __forceinline__ float mish_f(float x) {
    if (x > 15.f) return x;
    float e = __expf(x);
    float t = e * (e + 2.f);
    return __fdividef(x * t, t + 2.f);
}

__device__ __forceinline__ void ffma2(unsigned long long& d,
                                      unsigned long long a,
                                      unsigned long long b) {
    asm("fma.rn.f32x2 %0, %1, %2, %0;" : "+l"(d) : "l"(a), "l"(b));
}
__device__ __forceinline__ unsigned long long pack2(float x, float y) {
    unsigned long long r;
    asm("mov.b64 %0, {%1, %2};" : "=l"(r) : "f"(x), "f"(y));
    return r;
}

// ---------------- kernel 0: pack W[o,c,k] -> wp[(k*COUT+o)*CIN + c] ----------------
__global__ void pack_w(const float* __restrict__ W, float* __restrict__ wp,
                       int COUT, int CIN)
{
    int i = blockIdx.x * 256 + threadIdx.x;
    int tot = COUT * CIN * 3;
    if (i >= tot) return;
    int o = i / (CIN * 3);
    int rem = i - o * CIN * 3;
    int c = rem / 3;
    int k = rem - 3 * c;
    wp[(size_t)(k * COUT + o) * CIN + c] = W[i];
}

// ---------------- kernel 1: linear + BN + mish ----------------
__global__ __launch_bounds__(256)
void linear_kernel(const float* __restrict__ trees, const float* __restrict__ Wl,
                   const float* __restrict__ bl, const float* __restrict__ gamma,
                   const float* __restrict__ beta, const float* __restrict__ bmean,
                   const float* __restrict__ bvar, float* __restrict__ act0)
{
    const int m0 = blockIdx.x * 64;
    const int b0 = blockIdx.y * 64;
    __shared__ float As[16][65];
    __shared__ float Bs[16][65];
    const int tid = threadIdx.x, tx = tid & 15, ty = tid >> 4;
    float acc[4][4] = {};
    for (int k0 = 0; k0 < 512; k0 += 16) {
        #pragma unroll
        for (int i = tid; i < 64 * 16; i += 256) {
            int m = i >> 4, kk = i & 15;
            As[kk][m] = Wl[(size_t)(m0 + m) * 512 + k0 + kk];
        }
        #pragma unroll
        for (int i = tid; i < 64 * 16; i += 256) {
            int bb = i >> 4, kk = i & 15;
            Bs[kk][bb] = trees[(size_t)(b0 + bb) * 512 + k0 + kk];
        }
        __syncthreads();
        #pragma unroll
        for (int kk = 0; kk < 16; kk++) {
            float ra[4], rb[4];
            #pragma unroll
            for (int u = 0; u < 4; u++) ra[u] = As[kk][ty * 4 + u];
            #pragma unroll
            for (int v = 0; v < 4; v++) rb[v] = Bs[kk][tx * 4 + v];
            #pragma unroll
            for (int u = 0; u < 4; u++)
                #pragma unroll
                for (int v = 0; v < 4; v++)
                    acc[u][v] = fmaf(ra[u], rb[v], acc[u][v]);
        }
        __syncthreads();
    }
    #pragma unroll
    for (int u = 0; u < 4; u++) {
        int m = m0 + ty * 4 + u;
        float sc = rsqrtf(bvar[m] + 1e-5f) * gamma[m];
        float bm = bmean[m], bt = beta[m], bi = bl[m];
        #pragma unroll
        for (int v = 0; v < 4; v++) {
            int bb = b0 + tx * 4 + v;
            float y = acc[u][v] + bi;
            y = (y - bm) * sc + bt;
            act0[(size_t)bb * 4096 + m] = mish_f(y);
        }
    }
}

// ---------------- dense-factorized conv ----------------
// Y[(k,o), s] = sum_c Wp[k*COUT+o, c] * xf(X[b, c, s])   (dense GEMM, 96 rows/CTA)
// out[b, o, n] = (n==0)?0 : Y[0,o,i0(n)] + Y[1,o,i1(n)] + Y[2,o,i2(n)] + bias[o]
// XFORM: 0 = identity, 1 = (x-mean)*istd, 2 = mish((x-mean)*istd)
template<int CIN, int COUT, int XFORM>
__global__ __launch_bounds__(256, 1)
void conv_dense(const float* __restrict__ act, const int* __restrict__ idx,
                const float* __restrict__ wp, const float* __restrict__ bias,
                const float* __restrict__ mean, const float* __restrict__ istd,
                float* __restrict__ raw, double* __restrict__ stats)
{
    constexpr int KC   = (CIN < 32) ? CIN : 32;     // K-chunk
    constexpr int NC   = CIN / KC;
    constexpr int XR   = KC / 4;                    // float4/thread, X chunk
    constexpr int AV   = KC / 4;                    // float4 per A row
    constexpr int ATOT = 96 * AV;
    constexpr int AR   = (ATOT + 255) / 256;

    extern __shared__ float smem[];
    float*  Xs   = smem;                      // [2][KC][256]
    float*  As   = smem + 2 * KC * 256;       // [2][KC][96]
    float*  Ys   = smem;                      // [96][258] (aliases Xs/As after mainloop)
    int*    sidx = (int*)(smem + 24768);      // [768]
    double* red  = (double*)(smem + 24768 + 768);  // [512]

    const int b   = blockIdx.y;
    const int m0  = blockIdx.x * 32;
    const int tid = threadIdx.x;
    const int tx  = tid & 15, ty = tid >> 4;

    const float4* xsrc = (const float4*)(act + (size_t)b * CIN * 256);
    const float4* wp4  = (const float4*)wp;

    float mb = 0.f, isb = 1.f;
    if (XFORM) { mb = mean[b]; isb = istd[b]; }

    for (int i = tid; i < LIDX; i += 256) sidx[i] = idx[b * LIDX + i];

    unsigned long long acc[6][8];
    #pragma unroll
    for (int u = 0; u < 6; u++)
        #pragma unroll
        for (int q = 0; q < 8; q++) acc[u][q] = 0ULL;

    float4 xreg[XR];
    float4 areg[AR];

    auto ldg_chunk = [&](int c) {
        #pragma unroll
        for (int r = 0; r < XR; r++)
            xreg[r] = xsrc[c * (KC * 64) + tid + 256 * r];
        #pragma unroll
        for (int t = 0; t < AR; t++) {
            int i = tid + 256 * t;
            if (AR * 256 == ATOT || i < ATOT) {
                int r = i / AV, cc = i - r * AV;
                int k = r >> 5, o = r & 31;
                areg[t] = wp4[(size_t)(k * COUT + m0 + o) * (CIN / 4) + c * AV + cc];
            }
        }
    };

    auto sts_chunk = [&](int buf) {
        float* Xb = Xs + buf * KC * 256;
        #pragma unroll
        for (int r = 0; r < XR; r++) {
            float4 v = xreg[r];
            if (XFORM) {
                v.x = (v.x - mb) * isb; v.y = (v.y - mb) * isb;
                v.z = (v.z - mb) * isb; v.w = (v.w - mb) * isb;
                if (XFORM == 2) {
                    v.x = mish_f(v.x); v.y = mish_f(v.y);
                    v.z = mish_f(v.z); v.w = mish_f(v.w);
                }
            }
            ((float4*)Xb)[tid + 256 * r] = v;
        }
        float* Ab = As + buf * KC * 96;
        #pragma unroll
        for (int t = 0; t < AR; t++) {
            int i = tid + 256 * t;
            if (AR * 256 == ATOT || i < ATOT) {
                int r = i / AV, cc = i - r * AV;
                Ab[(cc * 4 + 0) * 96 + r] = areg[t].x;
                Ab[(cc * 4 + 1) * 96 + r] = areg[t].y;
                Ab[(cc * 4 + 2) * 96 + r] = areg[t].z;
                Ab[(cc * 4 + 3) * 96 + r] = areg[t].w;
            }
        }
    };

    auto fma_chunk = [&](int buf) {
        const unsigned long long* Bb =
            (const unsigned long long*)(Xs + buf * KC * 256);
        const float* Ab = As + buf * KC * 96 + ty * 6;
        #pragma unroll 8
        for (int kk = 0; kk < KC; kk++) {
            unsigned long long bf[8];
            #pragma unroll
            for (int q = 0; q < 8; q++) bf[q] = Bb[kk * 128 + tx + 16 * q];
            #pragma unroll
            for (int u = 0; u < 6; u++) {
                float a = Ab[kk * 96 + u];
                unsigned long long a2 = pack2(a, a);
                #pragma unroll
                for (int q = 0; q < 8; q++) ffma2(acc[u][q], a2, bf[q]);
            }
        }
    };

    // ---- software-pipelined main loop (LDG overlapped with FMA) ----
    ldg_chunk(0);
    sts_chunk(0);
    __syncthreads();
    for (int c = 0; c < NC; c++) {
        if (c + 1 < NC) ldg_chunk(c + 1);
        fma_chunk(c & 1);
        __syncthreads();
        if (c + 1 < NC) { sts_chunk((c + 1) & 1); __syncthreads(); }
    }

    // ---- epilogue: Y tile -> smem, gather, bias, stats ----
    #pragma unroll
    for (int u = 0; u < 6; u++) {
        unsigned long long* yrow =
            (unsigned long long*)(Ys + (ty * 6 + u) * 258);
        #pragma unroll
        for (int q = 0; q < 8; q++) yrow[tx + 16 * q] = acc[u][q];
    }
    __syncthreads();

    int j0 = 0, j1 = 0, j2 = 0;
    if (tid) {
        j0 = sidx[3 * tid - 3];
        j1 = sidx[3 * tid - 2];
        j2 = sidx[3 * tid - 1];
    }
    float bsum = 0.f, bssq = 0.f;
    float* outb = raw + ((size_t)b * COUT + m0) * 256;
    #pragma unroll 4
    for (int o = 0; o < 32; o++) {
        float v = 0.f;
        if (tid) {
            v = Ys[o * 258 + j0] + Ys[(32 + o) * 258 + j1] +
                Ys[(64 + o) * 258 + j2] + bias[m0 + o];
        }
        outb[o * 256 + tid] = v;
        bsum += v;
        bssq += v * v;
    }

    red[tid] = (double)bsum;
    red[256 + tid] = (double)bssq;
    __syncthreads();
    #pragma unroll
    for (int off = 128; off > 0; off >>= 1) {
        if (tid < off) {
            red[tid] += red[tid + off];
            red[256 + tid] += red[256 + tid + off];
        }
        __syncthreads();
    }
    if (tid == 0) {
        atomicAdd(&stats[b], red[0]);
        atomicAdd(&stats[BATCH + b], red[256]);
    }
}

// ---------------- finalize per-batch LN statistics ----------------
__global__ void finalize_kernel(const double* __restrict__ stats,
                                float* __restrict__ mean, float* __restrict__ istd,
                                double cnt)
{
    int b = threadIdx.x;
    double s = stats[b], ss = stats[BATCH + b];
    double m = s / cnt;
    double var = (ss - cnt * m * m) / (cnt - 1.0);
    if (var < 0.0) var = 0.0;
    mean[b] = (float)m;
    istd[b] = 1.f / ((float)sqrt(var) + 1e-5f);
}

// ---------------- final normalize + mish -> out ----------------
__global__ __launch_bounds__(256)
void norm_final(const float* __restrict__ raw, const float* __restrict__ mean,
                const float* __restrict__ istd, float* __restrict__ out)
{
    const int PER4 = 512 * 256 / 4;
    const int total4 = BATCH * PER4;
    const float4* src = reinterpret_cast<const float4*>(raw);
    float4* dst = reinterpret_cast<float4*>(out);
    for (int i = blockIdx.x * blockDim.x + threadIdx.x; i < total4;
         i += gridDim.x * blockDim.x) {
        int b = i / PER4;
        float mb = mean[b], isb = istd[b];
        float4 v = src[i];
        v.x = mish_f((v.x - mb) * isb);
        v.y = mish_f((v.y - mb) * isb);
        v.z = mish_f((v.z - mb) * isb);
        v.w = mish_f((v.w - mb) * isb);
        dst[i] = v;
    }
}

// ---------------- launch ----------------

static constexpr int CONV_SMEM = (24768 + 768) * 4 + 512 * 8;  // 106240 B

extern "C" void kernel_launch(void* const* d_in, const int* in_sizes, int n_in,
                              void* d_out, int out_size)
{
    (void)in_sizes; (void)n_in; (void)out_size;
    const float* trees   = (const float*)d_in[0];
    const int*   indexes = (const int*)d_in[1];
    const float* W_lin   = (const float*)d_in[2];
    const float* b_lin   = (const float*)d_in[3];
    const float* bn_g    = (const float*)d_in[4];
    const float* bn_b    = (const float*)d_in[5];
    const float* bn_m    = (const float*)d_in[6];
    const float* bn_v    = (const float*)d_in[7];
    float* out = (float*)d_out;

    float *bufA, *bufB, *gmean, *gistd, *wpack;
    double* stats;
    cudaGetSymbolAddress((void**)&bufA,  g_bufA);
    cudaGetSymbolAddress((void**)&bufB,  g_bufB);
    cudaGetSymbolAddress((void**)&gmean, g_mean);
    cudaGetSymbolAddress((void**)&gistd, g_istd);
    cudaGetSymbolAddress((void**)&wpack, g_wpack);
    cudaGetSymbolAddress((void**)&stats, g_stats);

    cudaFuncSetAttribute(conv_dense<16, 32, 0>,
        cudaFuncAttributeMaxDynamicSharedMemorySize, CONV_SMEM);
    cudaFuncSetAttribute(conv_dense<32, 64, 1>,
        cudaFuncAttributeMaxDynamicSharedMemorySize, CONV_SMEM);
    cudaFuncSetAttribute(conv_dense<64, 128, 2>,
        cudaFuncAttributeMaxDynamicSharedMemorySize, CONV_SMEM);
    cudaFuncSetAttribute(conv_dense<128, 256, 2>,
        cudaFuncAttributeMaxDynamicSharedMemorySize, CONV_SMEM);
    cudaFuncSetAttribute(conv_dense<256, 512, 2>,
        cudaFuncAttributeMaxDynamicSharedMemorySize, CONV_SMEM);
    cudaFuncSetAttribute(conv_dense<512, 512, 2>,
        cudaFuncAttributeMaxDynamicSharedMemorySize, CONV_SMEM);

    // Pack all 6 weight tensors: wp[(k*COUT+o)*CIN + c] = W[o,c,k]
    static const int CH[7]    = {16, 32, 64, 128, 256, 512, 512};
    static const int WPOFF[6] = {0, 1536, 7680, 32256, 130560, 523776};
    for (int i = 0; i < 6; i++) {
        int cin = CH[i], cout = CH[i + 1];
        int tot = cout * cin * 3;
        pack_w<<<(tot + 255) / 256, 256>>>((const float*)d_in[8 + 2 * i],
                                           wpack + WPOFF[i], cout, cin);
    }

    // linear + BN + mish -> bufA (viewed as (B, 16, 256))
    linear_kernel<<<dim3(64, 4), 256>>>(
        trees, W_lin, b_lin, bn_g, bn_b, bn_m, bn_v, bufA);

#define CONVL(I, CIN, COUT, XF, SRC, DST)                                         \
    cudaMemsetAsync(stats, 0, sizeof(double) * 2 * BATCH);                        \
    conv_dense<CIN, COUT, XF>                                                     \
        <<<dim3(COUT / 32, BATCH), 256, CONV_SMEM>>>(                             \
            SRC, indexes, wpack + WPOFF[I],                                       \
            (const float*)d_in[9 + 2 * I], gmean, gistd, DST, stats);             \
    finalize_kernel<<<1, BATCH>>>(stats, gmean, gistd, (double)(COUT * 256));

    CONVL(0,  16,  32, 0, bufA, bufB)
    CONVL(1,  32,  64, 1, bufB, bufA)
    CONVL(2,  64, 128, 2, bufA, bufB)
    CONVL(3, 128, 256, 2, bufB, bufA)
    CONVL(4, 256, 512, 2, bufA, bufB)
    CONVL(5, 512, 512, 2, bufB, bufA)
#undef CONVL

    // final: out = mish(LN(raw5))
    norm_final<<<2048, 256>>>(bufA, gmean, gistd, out);
}

// round 17
// speedup vs baseline: 1.0063x; 1.0008x over previous
#include <cuda_runtime.h>
#include <math.h>
#include <stdint.h>

#define BATCH   256
#define LIDX    765

// Scratch (allocation-free __device__ globals)
__device__ float  g_bufA[33554432];
__device__ float  g_bufB[33554432];
__device__ float  g_wpack[1310720];   // packed weights, all 6 layers
__device__ double g_stats[2 * BATCH];
__device__ float  g_mean[BATCH];
__device__ float  g_istd[BATCH];

// ---------------- helpers ----------------

// mish(x) = x*tanh(softplus(x)) = x*(e^2+2e)/(e^2+2e+2), e = exp(x)
__device__ __forceinline__ float mish_f(float x) {
    if (x > 15.f) return x;
    float e = __expf(x);
    float t = e * (e + 2.f);
    return __fdividef(x * t, t + 2.f);
}

__device__ __forceinline__ void ffma2(unsigned long long& d,
                                      unsigned long long a,
                                      unsigned long long b) {
    asm("fma.rn.f32x2 %0, %1, %2, %0;" : "+l"(d) : "l"(a), "l"(b));
}
__device__ __forceinline__ unsigned long long pack2(float x, float y) {
    unsigned long long r;
    asm("mov.b64 %0, {%1, %2};" : "=l"(r) : "f"(x), "f"(y));
    return r;
}

// ---------------- kernel 0: pack W[o,c,k] -> wp[(k*COUT+o)*CIN + c] ----------------
__global__ void pack_w(const float* __restrict__ W, float* __restrict__ wp,
                       int COUT, int CIN)
{
    int i = blockIdx.x * 256 + threadIdx.x;
    int tot = COUT * CIN * 3;
    if (i >= tot) return;
    int o = i / (CIN * 3);
    int rem = i - o * CIN * 3;
    int c = rem / 3;
    int k = rem - 3 * c;
    wp[(size_t)(k * COUT + o) * CIN + c] = W[i];
}

// ---------------- kernel 1: linear + BN + mish ----------------
__global__ __launch_bounds__(256)
void linear_kernel(const float* __restrict__ trees, const float* __restrict__ Wl,
                   const float* __restrict__ bl, const float* __restrict__ gamma,
                   const float* __restrict__ beta, const float* __restrict__ bmean,
                   const float* __restrict__ bvar, float* __restrict__ act0)
{
    const int m0 = blockIdx.x * 64;
    const int b0 = blockIdx.y * 64;
    __shared__ float As[16][65];
    __shared__ float Bs[16][65];
    const int tid = threadIdx.x, tx = tid & 15, ty = tid >> 4;
    float acc[4][4] = {};
    for (int k0 = 0; k0 < 512; k0 += 16) {
        #pragma unroll
        for (int i = tid; i < 64 * 16; i += 256) {
            int m = i >> 4, kk = i & 15;
            As[kk][m] = Wl[(size_t)(m0 + m) * 512 + k0 + kk];
        }
        #pragma unroll
        for (int i = tid; i < 64 * 16; i += 256) {
            int bb = i >> 4, kk = i & 15;
            Bs[kk][bb] = trees[(size_t)(b0 + bb) * 512 + k0 + kk];
        }
        __syncthreads();
        #pragma unroll
        for (int kk = 0; kk < 16; kk++) {
            float ra[4], rb[4];
            #pragma unroll
            for (int u = 0; u < 4; u++) ra[u] = As[kk][ty * 4 + u];
            #pragma unroll
            for (int v = 0; v < 4; v++) rb[v] = Bs[kk][tx * 4 + v];
            #pragma unroll
            for (int u = 0; u < 4; u++)
                #pragma unroll
                for (int v = 0; v < 4; v++)
                    acc[u][v] = fmaf(ra[u], rb[v], acc[u][v]);
        }
        __syncthreads();
    }
    #pragma unroll
    for (int u = 0; u < 4; u++) {
        int m = m0 + ty * 4 + u;
        float sc = rsqrtf(bvar[m] + 1e-5f) * gamma[m];
        float bm = bmean[m], bt = beta[m], bi = bl[m];
        #pragma unroll
        for (int v = 0; v < 4; v++) {
            int bb = b0 + tx * 4 + v;
            float y = acc[u][v] + bi;
            y = (y - bm) * sc + bt;
            act0[(size_t)bb * 4096 + m] = mish_f(y);
        }
    }
}

// ---------------- dense-factorized conv ----------------
// Y[(k,o), s] = sum_c Wp[k*COUT+o, c] * xf(X[b, c, s])   (dense GEMM, 96 rows/CTA)
// out[b, o, n] = (n==0)?0 : Y[0,o,i0(n)] + Y[1,o,i1(n)] + Y[2,o,i2(n)] + bias[o]
// XFORM: 0 = identity, 1 = (x-mean)*istd, 2 = mish((x-mean)*istd)
template<int CIN, int COUT, int XFORM>
__global__ __launch_bounds__(256, 1)
void conv_dense(const float* __restrict__ act, const int* __restrict__ idx,
                const float* __restrict__ wp, const float* __restrict__ bias,
                const float* __restrict__ mean, const float* __restrict__ istd,
                float* __restrict__ raw, double* __restrict__ stats)
{
    constexpr int KC   = (CIN < 32) ? CIN : 32;     // K-chunk
    constexpr int NC   = CIN / KC;
    constexpr int XR   = KC / 4;                    // float4/thread, X chunk
    constexpr int AV   = KC / 4;                    // float4 per A row
    constexpr int ATOT = 96 * AV;
    constexpr int AR   = (ATOT + 255) / 256;

    extern __shared__ float smem[];
    float*  Xs   = smem;                      // [2][KC][256]
    float*  As   = smem + 2 * KC * 256;       // [2][KC][96]
    float*  Ys   = smem;                      // [96][258] (aliases Xs/As after mainloop)
    int*    sidx = (int*)(smem + 24768);      // [768]
    double* red  = (double*)(smem + 24768 + 768);  // [512]

    const int b   = blockIdx.y;
    const int m0  = blockIdx.x * 32;
    const int tid = threadIdx.x;
    const int tx  = tid & 15, ty = tid >> 4;

    const float4* xsrc = (const float4*)(act + (size_t)b * CIN * 256);
    const float4* wp4  = (const float4*)wp;

    float mb = 0.f, isb = 1.f;
    if (XFORM) { mb = mean[b]; isb = istd[b]; }

    for (int i = tid; i < LIDX; i += 256) sidx[i] = idx[b * LIDX + i];

    unsigned long long acc[6][8];
    #pragma unroll
    for (int u = 0; u < 6; u++)
        #pragma unroll
        for (int q = 0; q < 8; q++) acc[u][q] = 0ULL;

    float4 xreg[XR];
    float4 areg[AR];

    auto ldg_chunk = [&](int c) {
        #pragma unroll
        for (int r = 0; r < XR; r++)
            xreg[r] = xsrc[c * (KC * 64) + tid + 256 * r];
        #pragma unroll
        for (int t = 0; t < AR; t++) {
            int i = tid + 256 * t;
            if (AR * 256 == ATOT || i < ATOT) {
                int r = i / AV, cc = i - r * AV;
                int k = r >> 5, o = r & 31;
                areg[t] = wp4[(size_t)(k * COUT + m0 + o) * (CIN / 4) + c * AV + cc];
            }
        }
    };

    auto sts_chunk = [&](int buf) {
        float* Xb = Xs + buf * KC * 256;
        #pragma unroll
        for (int r = 0; r < XR; r++) {
            float4 v = xreg[r];
            if (XFORM) {
                v.x = (v.x - mb) * isb; v.y = (v.y - mb) * isb;
                v.z = (v.z - mb) * isb; v.w = (v.w - mb) * isb;
                if (XFORM == 2) {
                    v.x = mish_f(v.x); v.y = mish_f(v.y);
                    v.z = mish_f(v.z); v.w = mish_f(v.w);
                }
            }
            ((float4*)Xb)[tid + 256 * r] = v;
        }
        float* Ab = As + buf * KC * 96;
        #pragma unroll
        for (int t = 0; t < AR; t++) {
            int i = tid + 256 * t;
            if (AR * 256 == ATOT || i < ATOT) {
                int r = i / AV, cc = i - r * AV;
                Ab[(cc * 4 + 0) * 96 + r] = areg[t].x;
                Ab[(cc * 4 + 1) * 96 + r] = areg[t].y;
                Ab[(cc * 4 + 2) * 96 + r] = areg[t].z;
                Ab[(cc * 4 + 3) * 96 + r] = areg[t].w;
            }
        }
    };

    auto fma_chunk = [&](int buf) {
        const unsigned long long* Bb =
            (const unsigned long long*)(Xs + buf * KC * 256);
        const float* Ab = As + buf * KC * 96 + ty * 6;
        #pragma unroll 8
        for (int kk = 0; kk < KC; kk++) {
            unsigned long long bf[8];
            #pragma unroll
            for (int q = 0; q < 8; q++) bf[q] = Bb[kk * 128 + tx + 16 * q];
            #pragma unroll
            for (int u = 0; u < 6; u++) {
                float a = Ab[kk * 96 + u];
                unsigned long long a2 = pack2(a, a);
                #pragma unroll
                for (int q = 0; q < 8; q++) ffma2(acc[u][q], a2, bf[q]);
            }
        }
    };

    // ---- software-pipelined main loop (LDG overlapped with FMA) ----
    ldg_chunk(0);
    sts_chunk(0);
    __syncthreads();
    for (int c = 0; c < NC; c++) {
        if (c + 1 < NC) ldg_chunk(c + 1);
        fma_chunk(c & 1);
        __syncthreads();
        if (c + 1 < NC) { sts_chunk((c + 1) & 1); __syncthreads(); }
    }

    // ---- epilogue: Y tile -> smem, gather, bias, stats ----
    #pragma unroll
    for (int u = 0; u < 6; u++) {
        unsigned long long* yrow =
            (unsigned long long*)(Ys + (ty * 6 + u) * 258);
        #pragma unroll
        for (int q = 0; q < 8; q++) yrow[tx + 16 * q] = acc[u][q];
    }
    __syncthreads();

    int j0 = 0, j1 = 0, j2 = 0;
    if (tid) {
        j0 = sidx[3 * tid - 3];
        j1 = sidx[3 * tid - 2];
        j2 = sidx[3 * tid - 1];
    }
    float bsum = 0.f, bssq = 0.f;
    float* outb = raw + ((size_t)b * COUT + m0) * 256;
    #pragma unroll 4
    for (int o = 0; o < 32; o++) {
        float v = 0.f;
        if (tid) {
            v = Ys[o * 258 + j0] + Ys[(32 + o) * 258 + j1] +
                Ys[(64 + o) * 258 + j2] + bias[m0 + o];
        }
        outb[o * 256 + tid] = v;
        bsum += v;
        bssq += v * v;
    }

    red[tid] = (double)bsum;
    red[256 + tid] = (double)bssq;
    __syncthreads();
    #pragma unroll
    for (int off = 128; off > 0; off >>= 1) {
        if (tid < off) {
            red[tid] += red[tid + off];
            red[256 + tid] += red[256 + tid + off];
        }
        __syncthreads();
    }
    if (tid == 0) {
        atomicAdd(&stats[b], red[0]);
        atomicAdd(&stats[BATCH + b], red[256]);
    }
}

// ---------------- finalize per-batch LN statistics ----------------
__global__ void finalize_kernel(const double* __restrict__ stats,
                                float* __restrict__ mean, float* __restrict__ istd,
                                double cnt)
{
    int b = threadIdx.x;
    double s = stats[b], ss = stats[BATCH + b];
    double m = s / cnt;
    double var = (ss - cnt * m * m) / (cnt - 1.0);
    if (var < 0.0) var = 0.0;
    mean[b] = (float)m;
    istd[b] = 1.f / ((float)sqrt(var) + 1e-5f);
}

// ---------------- final normalize + mish -> out ----------------
__global__ __launch_bounds__(256)
void norm_final(const float* __restrict__ raw, const float* __restrict__ mean,
                const float* __restrict__ istd, float* __restrict__ out)
{
    const int PER4 = 512 * 256 / 4;
    const int total4 = BATCH * PER4;
    const float4* src = reinterpret_cast<const float4*>(raw);
    float4* dst = reinterpret_cast<float4*>(out);
    for (int i = blockIdx.x * blockDim.x + threadIdx.x; i < total4;
         i += gridDim.x * blockDim.x) {
        int b = i / PER4;
        float mb = mean[b], isb = istd[b];
        float4 v = src[i];
        v.x = mish_f((v.x - mb) * isb);
        v.y = mish_f((v.y - mb) * isb);
        v.z = mish_f((v.z - mb) * isb);
        v.w = mish_f((v.w - mb) * isb);
        dst[i] = v;
    }
}

// ---------------- launch ----------------

static constexpr int CONV_SMEM = (24768 + 768) * 4 + 512 * 8;  // 106240 B

extern "C" void kernel_launch(void* const* d_in, const int* in_sizes, int n_in,
                              void* d_out, int out_size)
{
    (void)in_sizes; (void)n_in; (void)out_size;
    const float* trees   = (const float*)d_in[0];
    const int*   indexes = (const int*)d_in[1];
    const float* W_lin   = (const float*)d_in[2];
    const float* b_lin   = (const float*)d_in[3];
    const float* bn_g    = (const float*)d_in[4];
    const float* bn_b    = (const float*)d_in[5];
    const float* bn_m    = (const float*)d_in[6];
    const float* bn_v    = (const float*)d_in[7];
    float* out = (float*)d_out;

    float *bufA, *bufB, *gmean, *gistd, *wpack;
    double* stats;
    cudaGetSymbolAddress((void**)&bufA,  g_bufA);
    cudaGetSymbolAddress((void**)&bufB,  g_bufB);
    cudaGetSymbolAddress((void**)&gmean, g_mean);
    cudaGetSymbolAddress((void**)&gistd, g_istd);
    cudaGetSymbolAddress((void**)&wpack, g_wpack);
    cudaGetSymbolAddress((void**)&stats, g_stats);

    cudaFuncSetAttribute(conv_dense<16, 32, 0>,
        cudaFuncAttributeMaxDynamicSharedMemorySize, CONV_SMEM);
    cudaFuncSetAttribute(conv_dense<32, 64, 1>,
        cudaFuncAttributeMaxDynamicSharedMemorySize, CONV_SMEM);
    cudaFuncSetAttribute(conv_dense<64, 128, 2>,
        cudaFuncAttributeMaxDynamicSharedMemorySize, CONV_SMEM);
    cudaFuncSetAttribute(conv_dense<128, 256, 2>,
        cudaFuncAttributeMaxDynamicSharedMemorySize, CONV_SMEM);
    cudaFuncSetAttribute(conv_dense<256, 512, 2>,
        cudaFuncAttributeMaxDynamicSharedMemorySize, CONV_SMEM);
    cudaFuncSetAttribute(conv_dense<512, 512, 2>,
        cudaFuncAttributeMaxDynamicSharedMemorySize, CONV_SMEM);

    // Pack all 6 weight tensors: wp[(k*COUT+o)*CIN + c] = W[o,c,k]
    static const int CH[7]    = {16, 32, 64, 128, 256, 512, 512};
    static const int WPOFF[6] = {0, 1536, 7680, 32256, 130560, 523776};
    for (int i = 0; i < 6; i++) {
        int cin = CH[i], cout = CH[i + 1];
        int tot = cout * cin * 3;
        pack_w<<<(tot + 255) / 256, 256>>>((const float*)d_in[8 + 2 * i],
                                           wpack + WPOFF[i], cout, cin);
    }

    // linear + BN + mish -> bufA (viewed as (B, 16, 256))
    linear_kernel<<<dim3(64, 4), 256>>>(
        trees, W_lin, b_lin, bn_g, bn_b, bn_m, bn_v, bufA);

#define CONVL(I, CIN, COUT, XF, SRC, DST)                                         \
    cudaMemsetAsync(stats, 0, sizeof(double) * 2 * BATCH);                        \
    conv_dense<CIN, COUT, XF>                                                     \
        <<<dim3(COUT / 32, BATCH), 256, CONV_SMEM>>>(                             \
            SRC, indexes, wpack + WPOFF[I],                                       \
            (const float*)d_in[9 + 2 * I], gmean, gistd, DST, stats);             \
    finalize_kernel<<<1, BATCH>>>(stats, gmean, gistd, (double)(COUT * 256));

    CONVL(0,  16,  32, 0, bufA, bufB)
    CONVL(1,  32,  64, 1, bufB, bufA)
    CONVL(2,  64, 128, 2, bufA, bufB)
    CONVL(3, 128, 256, 2, bufB, bufA)
    CONVL(4, 256, 512, 2, bufA, bufB)
    CONVL(5, 512, 512, 2, bufB, bufA)
#undef CONVL

    // final: out = mish(LN(raw5))
    norm_final<<<2048, 256>>>(bufA, gmean, gistd, out);
}